// round 16
// baseline (speedup 1.0000x reference)
#include <cuda_runtime.h>
#include <cuda_bf16.h>

// Problem constants (shapes are fixed by the dataset)
#define D_STEPS 71
#define FH      32
#define FW      64
#define NPTS    (D_STEPS * FH * FW)   // 145408
#define HWN     (FH * FW)             // 2048 (power of two)
#define NXX     600
#define NXY     300
#define NVOX    (NXX * NXY)           // 180000
#define NCH     128

// Per-voxel "last point index" table. -1 == empty voxel.
__device__ __align__(16) int g_last[NVOX];

// ---------------------------------------------------------------------------
// Kernel 0: reset the argmax table (must happen every replay; graph-captured)
// ---------------------------------------------------------------------------
__global__ void lss_fill_kernel() {
    int v = blockIdx.x * blockDim.x + threadIdx.x;
    if (v < NVOX) g_last[v] = -1;
}

// ---------------------------------------------------------------------------
// Kernel 1: project each frustum point, compute its voxel, atomicMax the index.
// FP ordering hypothesis: SLP-vectorized reduce (llvm.vector.reduce.fadd on a
// <4 x float> of plain products) = stride-2 halving tree:
//   g = rn( rn(m0*p0 + m2*p2) + rn(m1*p1 + m3*1) )
// ---------------------------------------------------------------------------
__global__ void lss_rank_kernel(const float* __restrict__ frustum,
                                const float* __restrict__ invm) {
    int i = blockIdx.x * blockDim.x + threadIdx.x;
    if (i >= NPTS) return;

    float fx = __ldg(frustum + 3 * i + 0);
    float fy = __ldg(frustum + 3 * i + 1);
    float fd = __ldg(frustum + 3 * i + 2);

    // pts = [fx*fd*(1700/512), fy*fd*(3517/1024), fd, 1]
    // Both scale constants are exactly representable in fp32.
    float p0 = __fmul_rn(__fmul_rn(fx, fd), 3.3203125f);
    float p1 = __fmul_rn(__fmul_rn(fy, fd), 3.4345703125f);
    float p2 = fd;

    // inv_m rows 0..2 (uniform across warp; cache resident)
    float m00 = __ldg(invm + 0),  m01 = __ldg(invm + 1),
          m02 = __ldg(invm + 2),  m03 = __ldg(invm + 3);
    float m10 = __ldg(invm + 4),  m11 = __ldg(invm + 5),
          m12 = __ldg(invm + 6),  m13 = __ldg(invm + 7);
    float m20 = __ldg(invm + 8),  m21 = __ldg(invm + 9),
          m22 = __ldg(invm + 10), m23 = __ldg(invm + 11);

    // Stride-2 halving-shuffle reduction tree: (t0 + t2) + (t1 + t3)
    float g0 = __fadd_rn(__fadd_rn(__fmul_rn(m00, p0), __fmul_rn(m02, p2)),
                         __fadd_rn(__fmul_rn(m01, p1), m03));
    float g1 = __fadd_rn(__fadd_rn(__fmul_rn(m10, p0), __fmul_rn(m12, p2)),
                         __fadd_rn(__fmul_rn(m11, p1), m13));
    float g2 = __fadd_rn(__fadd_rn(__fmul_rn(m20, p0), __fmul_rn(m22, p2)),
                         __fadd_rn(__fmul_rn(m21, p1), m23));

    // gidx = (geom - (bx - dx/2)) / dx, truncated toward zero (int32 cast).
    // bx - dx/2 = (-75, 0, -10) exactly in fp32.
    int gx = (int)__fdiv_rn(__fsub_rn(g0, -75.0f), 0.25f);
    int gy = (int)__fdiv_rn(__fsub_rn(g1,   0.0f), 0.25f);
    int gz = (int)__fdiv_rn(__fsub_rn(g2, -10.0f), 20.0f);

    if (gx >= 0 && gx < NXX && gy >= 0 && gy < NXY && gz == 0) {
        atomicMax(&g_last[gx * NXY + gy], i);
    }
}

// ---------------------------------------------------------------------------
// Kernel 2: scatter features. out[c, gx, gy] = x[c, last % 2048] or 0.
// float4-vectorized along gy-fastest voxel dim; output write (92 MB) is the
// only DRAM traffic — per-channel 8 KB slice of x is L1-resident per block,
// g_last (720 KB) stays in L2.
// ---------------------------------------------------------------------------
__global__ void lss_write_kernel(const float* __restrict__ x,
                                 float* __restrict__ out) {
    int v4 = blockIdx.x * blockDim.x + threadIdx.x;   // voxel-quad index
    if (v4 >= NVOX / 4) return;
    int c = blockIdx.y;                               // channel 0..127

    int4 l = *(((const int4*)g_last) + v4);
    const float* __restrict__ xc = x + c * HWN;

    float4 o;
    o.x = (l.x >= 0) ? __ldg(xc + (l.x & (HWN - 1))) : 0.0f;
    o.y = (l.y >= 0) ? __ldg(xc + (l.y & (HWN - 1))) : 0.0f;
    o.z = (l.z >= 0) ? __ldg(xc + (l.z & (HWN - 1))) : 0.0f;
    o.w = (l.w >= 0) ? __ldg(xc + (l.w & (HWN - 1))) : 0.0f;

    ((float4*)out)[(size_t)c * (NVOX / 4) + v4] = o;
}

// ---------------------------------------------------------------------------
// Launch
// ---------------------------------------------------------------------------
extern "C" void kernel_launch(void* const* d_in, const int* in_sizes, int n_in,
                              void* d_out, int out_size) {
    const float* x       = (const float*)d_in[0];  // (1,1,128,32,64) = 262144
    const float* frustum = (const float*)d_in[1];  // (71,32,64,3)    = 436224
    const float* invm    = (const float*)d_in[2];  // (4,4)           = 16
    float* out = (float*)d_out;                    // (1,128,600,300)

    (void)in_sizes; (void)n_in; (void)out_size;

    // 0) reset argmax table
    lss_fill_kernel<<<(NVOX + 255) / 256, 256>>>();

    // 1) project + per-voxel last-index argmax
    lss_rank_kernel<<<(NPTS + 255) / 256, 256>>>(frustum, invm);

    // 2) scatter features (DRAM-write-bound)
    dim3 grid((NVOX / 4 + 255) / 256, NCH);
    lss_write_kernel<<<grid, 256>>>(x, out);
}

// round 17
// speedup vs baseline: 1.1581x; 1.1581x over previous
#include <cuda_runtime.h>
#include <cuda_bf16.h>

// Problem constants (shapes are fixed by the dataset)
#define D_STEPS 71
#define FH      32
#define FW      64
#define NPTS    (D_STEPS * FH * FW)   // 145408
#define HWN     (FH * FW)             // 2048 (power of two)
#define NXX     600
#define NXY     300
#define NVOX    (NXX * NXY)           // 180000
#define NCH     128
#define CH_PER_BLK 16                 // grid.y = NCH / CH_PER_BLK = 8

// Per-voxel "last point index" table. -1 == empty voxel. Reset via memset node.
__device__ __align__(16) int g_last[NVOX];

// ---------------------------------------------------------------------------
// Kernel 1: project each frustum point, compute its voxel, atomicMax the index.
// FP ordering (verified EXACT vs reference): SLP stride-2 halving tree:
//   g = rn( rn(m0*p0 + m2*p2) + rn(m1*p1 + m3) )
// ---------------------------------------------------------------------------
__global__ void lss_rank_kernel(const float* __restrict__ frustum,
                                const float* __restrict__ invm) {
    int i = blockIdx.x * blockDim.x + threadIdx.x;
    if (i >= NPTS) return;

    float fx = __ldg(frustum + 3 * i + 0);
    float fy = __ldg(frustum + 3 * i + 1);
    float fd = __ldg(frustum + 3 * i + 2);

    // pts = [fx*fd*(1700/512), fy*fd*(3517/1024), fd, 1]; scales exact in fp32
    float p0 = __fmul_rn(__fmul_rn(fx, fd), 3.3203125f);
    float p1 = __fmul_rn(__fmul_rn(fy, fd), 3.4345703125f);
    float p2 = fd;

    float m00 = __ldg(invm + 0),  m01 = __ldg(invm + 1),
          m02 = __ldg(invm + 2),  m03 = __ldg(invm + 3);
    float m10 = __ldg(invm + 4),  m11 = __ldg(invm + 5),
          m12 = __ldg(invm + 6),  m13 = __ldg(invm + 7);
    float m20 = __ldg(invm + 8),  m21 = __ldg(invm + 9),
          m22 = __ldg(invm + 10), m23 = __ldg(invm + 11);

    // Stride-2 halving-shuffle reduction tree: (t0 + t2) + (t1 + t3)  [EXACT]
    float g0 = __fadd_rn(__fadd_rn(__fmul_rn(m00, p0), __fmul_rn(m02, p2)),
                         __fadd_rn(__fmul_rn(m01, p1), m03));
    float g1 = __fadd_rn(__fadd_rn(__fmul_rn(m10, p0), __fmul_rn(m12, p2)),
                         __fadd_rn(__fmul_rn(m11, p1), m13));
    float g2 = __fadd_rn(__fadd_rn(__fmul_rn(m20, p0), __fmul_rn(m22, p2)),
                         __fadd_rn(__fmul_rn(m21, p1), m23));

    // gidx = (geom - (bx - dx/2)) / dx, truncated toward zero (int32 cast).
    int gx = (int)__fdiv_rn(__fsub_rn(g0, -75.0f), 0.25f);
    int gy = (int)__fdiv_rn(__fsub_rn(g1,   0.0f), 0.25f);
    int gz = (int)__fdiv_rn(__fsub_rn(g2, -10.0f), 20.0f);

    if (gx >= 0 && gx < NXX && gy >= 0 && gy < NXY && gz == 0) {
        atomicMax(&g_last[gx * NXY + gy], i);
    }
}

// ---------------------------------------------------------------------------
// Kernel 2: scatter features. out[c, v] = x[c, g_last[v] & 2047] or 0.
// Each thread owns one voxel-quad: decodes g_last ONCE, then loops over its
// CH_PER_BLK channel slice. Stores are coalesced float4; x (1 MB) and g_last
// (720 KB, read 8x total) live in L2 — output write is the only DRAM traffic.
// ---------------------------------------------------------------------------
__global__ void lss_write_kernel(const float* __restrict__ x,
                                 float* __restrict__ out) {
    int v4 = blockIdx.x * blockDim.x + threadIdx.x;   // voxel-quad index
    if (v4 >= NVOX / 4) return;

    int4 l = *(((const int4*)g_last) + v4);
    int  i0 = l.x & (HWN - 1), i1 = l.y & (HWN - 1);
    int  i2 = l.z & (HWN - 1), i3 = l.w & (HWN - 1);
    bool b0 = l.x >= 0, b1 = l.y >= 0, b2 = l.z >= 0, b3 = l.w >= 0;

    int c0 = blockIdx.y * CH_PER_BLK;
    const float* __restrict__ xc = x + (size_t)c0 * HWN;
    float4* __restrict__ op = (float4*)out + (size_t)c0 * (NVOX / 4) + v4;

    #pragma unroll 4
    for (int c = 0; c < CH_PER_BLK; c++) {
        float4 o;
        o.x = b0 ? __ldg(xc + i0) : 0.0f;
        o.y = b1 ? __ldg(xc + i1) : 0.0f;
        o.z = b2 ? __ldg(xc + i2) : 0.0f;
        o.w = b3 ? __ldg(xc + i3) : 0.0f;
        *op = o;
        xc += HWN;
        op += NVOX / 4;
    }
}

// ---------------------------------------------------------------------------
// Launch
// ---------------------------------------------------------------------------
extern "C" void kernel_launch(void* const* d_in, const int* in_sizes, int n_in,
                              void* d_out, int out_size) {
    const float* x       = (const float*)d_in[0];  // (1,1,128,32,64) = 262144
    const float* frustum = (const float*)d_in[1];  // (71,32,64,3)    = 436224
    const float* invm    = (const float*)d_in[2];  // (4,4)           = 16
    float* out = (float*)d_out;                    // (1,128,600,300)

    (void)in_sizes; (void)n_in; (void)out_size;

    // 0) reset argmax table via memset node (0xFF bytes -> int -1)
    void* last_ptr = nullptr;
    cudaGetSymbolAddress(&last_ptr, g_last);
    cudaMemsetAsync(last_ptr, 0xFF, NVOX * sizeof(int));

    // 1) project + per-voxel last-index argmax
    lss_rank_kernel<<<(NPTS + 255) / 256, 256>>>(frustum, invm);

    // 2) scatter features (DRAM-write-bound)
    dim3 grid((NVOX / 4 + 255) / 256, NCH / CH_PER_BLK);
    lss_write_kernel<<<grid, 256>>>(x, out);
}